// round 1
// baseline (speedup 1.0000x reference)
#include <cuda_runtime.h>

#define ORDER 32
#define EPSV 1e-5f

__global__ __launch_bounds__(256)
void levinson_kernel(const float* __restrict__ pAC,
                     float* __restrict__ out,
                     int T)
{
    int t = blockIdx.x * blockDim.x + threadIdx.x;
    if (t >= T) return;

    float ac[ORDER + 1];
    float lp[ORDER];

    ac[0] = pAC[t];
    float E = ac[0];

#pragma unroll
    for (int i = 0; i < ORDER; i++) {
        // lazy-load the next lag; by iteration i we have ac[0..i+1]
        ac[i + 1] = pAC[(i + 1) * T + t];

        // acc = ac[i+1] + sum_{j=0}^{i-1} lp[j] * ac[i-j]
        float acc = ac[i + 1];
#pragma unroll
        for (int j = 0; j < i; j++) {
            acc = fmaf(lp[j], ac[i - j], acc);
        }

        float ki = __fdividef(acc, E);
        float c  = fmaf(-ki, ki, 1.0f);
        c = fmaxf(c, EPSV);
        E = E * c;

        // lp[j] = lp[j] - ki * lp_old[i-1-j]  (symmetric in-place pair update)
#pragma unroll
        for (int j = 0; j < i / 2; j++) {
            float a = lp[j];
            float b = lp[i - 1 - j];
            lp[j]         = fmaf(-ki, b, a);
            lp[i - 1 - j] = fmaf(-ki, a, b);
        }
        if (i & 1) {
            int m = (i - 1) / 2;   // self-paired middle element
            lp[m] = fmaf(-ki, lp[m], lp[m]);
        }

        lp[i] = -ki;
    }

#pragma unroll
    for (int i = 0; i < ORDER; i++) {
        out[i * T + t] = lp[i];
    }
}

extern "C" void kernel_launch(void* const* d_in, const int* in_sizes, int n_in,
                              void* d_out, int out_size)
{
    const float* pAC = (const float*)d_in[0];
    float* out = (float*)d_out;
    int T = in_sizes[0] / (ORDER + 1);   // pAC is [1, N+1, T]

    int threads = 256;
    int blocks = (T + threads - 1) / threads;
    levinson_kernel<<<blocks, threads>>>(pAC, out, T);
}

// round 2
// speedup vs baseline: 1.0707x; 1.0707x over previous
#include <cuda_runtime.h>

#define ORDER 32
#define EPSV 1e-5f

typedef unsigned long long u64;

// ---- packed f32x2 helpers (sm_103a-only packed FMA pipe) ----
__device__ __forceinline__ u64 fma2(u64 a, u64 b, u64 c) {
    u64 d;
    asm("fma.rn.f32x2 %0, %1, %2, %3;" : "=l"(d) : "l"(a), "l"(b), "l"(c));
    return d;
}
__device__ __forceinline__ u64 add2(u64 a, u64 b) {
    u64 d;
    asm("add.rn.f32x2 %0, %1, %2;" : "=l"(d) : "l"(a), "l"(b));
    return d;
}
__device__ __forceinline__ u64 pack2(float lo, float hi) {
    u64 r;
    asm("mov.b64 %0, {%1, %2};" : "=l"(r) : "f"(lo), "f"(hi));
    return r;
}
__device__ __forceinline__ void unpack2(u64 v, float& lo, float& hi) {
    asm("mov.b64 {%0, %1}, %2;" : "=f"(lo), "=f"(hi) : "l"(v));
}

__global__ __launch_bounds__(128, 3)
void levinson_kernel2(const u64* __restrict__ pAC2,  // [33, T/2] as packed frame pairs
                      u64* __restrict__ out2,        // [32, T/2]
                      int Th)                        // T/2
{
    int t = blockIdx.x * blockDim.x + threadIdx.x;
    if (t >= Th) return;

    u64 ac[ORDER + 1];   // packed: two adjacent frames per thread
    u64 lp[ORDER];

    ac[0] = pAC2[t];
    float E0, E1;
    unpack2(ac[0], E0, E1);

#pragma unroll
    for (int i = 0; i < ORDER; i++) {
        // lazy-load next lag (coalesced 8B loads across the warp)
        ac[i + 1] = pAC2[(i + 1) * Th + t];

        // acc = ac[i+1] + sum_{j<i} lp[j] * ac[i-j], dual packed accumulators
        u64 acc0 = ac[i + 1];
        u64 acc1 = 0ull;  // packed (+0.0f, +0.0f)
#pragma unroll
        for (int j = 0; j < i; j += 2) {
            acc0 = fma2(lp[j], ac[i - j], acc0);
            if (j + 1 < i) acc1 = fma2(lp[j + 1], ac[i - j - 1], acc1);
        }
        u64 accp = (i > 1) ? add2(acc0, acc1) : acc0;

        float a0, a1;
        unpack2(accp, a0, a1);

        // per-lane scalar: reflection coeff + energy update
        float ki0 = __fdividef(a0, E0);
        float ki1 = __fdividef(a1, E1);
        float c0 = fmaxf(fmaf(-ki0, ki0, 1.0f), EPSV);
        float c1 = fmaxf(fmaf(-ki1, ki1, 1.0f), EPSV);
        E0 *= c0;
        E1 *= c1;

        u64 nki = pack2(-ki0, -ki1);

        // lp[j] = lp[j] - ki * lp_old[i-1-j]  (symmetric in-place pair update)
#pragma unroll
        for (int j = 0; j < i / 2; j++) {
            u64 a = lp[j];
            u64 b = lp[i - 1 - j];
            lp[j]         = fma2(nki, b, a);
            lp[i - 1 - j] = fma2(nki, a, b);
        }
        if (i & 1) {
            int m = (i - 1) / 2;
            lp[m] = fma2(nki, lp[m], lp[m]);
        }

        lp[i] = nki;
    }

#pragma unroll
    for (int i = 0; i < ORDER; i++) {
        out2[i * Th + t] = lp[i];
    }
}

extern "C" void kernel_launch(void* const* d_in, const int* in_sizes, int n_in,
                              void* d_out, int out_size)
{
    const u64* pAC2 = (const u64*)d_in[0];
    u64* out2 = (u64*)d_out;
    int T = in_sizes[0] / (ORDER + 1);   // pAC is [1, N+1, T]; T is even (2^20)
    int Th = T / 2;

    int threads = 128;
    int blocks = (Th + threads - 1) / threads;
    levinson_kernel2<<<blocks, threads>>>(pAC2, out2, Th);
}